// round 3
// baseline (speedup 1.0000x reference)
#include <cuda_runtime.h>
#include <cstdint>

#define CDIV(a,b) (((a)+(b)-1)/(b))

constexpr int Nn  = 50000;
constexpr int Ed  = 256;
constexpr int Hd  = 512;
constexpr int NEx = 5;
constexpr int GHd = 128;
constexpr int CC  = 768;   // 3*Ed

// ---------------- scratch (static device globals; no allocation) -------------
__device__ float g_ghid[(size_t)Nn * GHd];           // 25.6 MB
__device__ int   g_lists[NEx * Nn];                  // routing lists (per-expert segment of Nn)
__device__ float g_gatew[NEx * Nn];                  // gate weight per assignment
__device__ int   g_counts[NEx];
__device__ float g_h1[(size_t)NEx * Nn * Hd];        // expert hidden
__device__ float g_nf[(size_t)Nn * Hd];              // node_feats (h^0)
__device__ float g_hw[(size_t)Nn * Hd];              // h @ Wnbr
__device__ float g_msg[(size_t)Nn * Hd];             // segment sum
__device__ float g_hl[(size_t)Nn * Hd];              // h after layer 0

// ---------------- helpers ----------------------------------------------------
__device__ __forceinline__ float gelu_f(float x) {
    float t = tanhf(0.7978845608028654f * (x + 0.044715f * x * x * x));
    return 0.5f * x * (1.0f + t);
}

// packed dual fp32 FMA (SASS FFMA2) — ptxas will not auto-fuse; PTX only.
__device__ __forceinline__ unsigned long long ffma2(
    unsigned long long a, unsigned long long b, unsigned long long c)
{
    unsigned long long d;
    asm("fma.rn.f32x2 %0, %1, %2, %3;" : "=l"(d) : "l"(a), "l"(b), "l"(c));
    return d;
}

// ---------------- SGEMM core: 128x128 tile, BK=8, 256 thr, 8x8/thread --------
// FFMA2 inner loop: A tile stored duplicated ((a,a) pairs) so packed operands
// load straight from smem; B pairs reinterpret the float4 loads.
// NSRC==3: A is the virtual concat [A0|A1|A2], each Nn x 256 row-major.
template<int NSRC, bool GATHER>
__device__ __forceinline__ void gemm_core(
    const float* __restrict__ A0, const float* __restrict__ A1,
    const float* __restrict__ A2, const float* __restrict__ B,
    const int* __restrict__ rowlist, int M, int K, int lda, int ldb,
    unsigned long long (&acc)[8][4])
{
    __shared__ float As2[8][256];   // duplicated pairs: As2[k][2r] == As2[k][2r+1]
    __shared__ float Bs[8][128];

    const int tid = threadIdx.x;
    const int tx = tid & 15, ty = tid >> 4;
    const int row0 = blockIdx.y * 128;
    const int col0 = blockIdx.x * 128;
    const int lr  = tid >> 1;        // 0..127
    const int lk  = (tid & 1) << 2;  // 0 or 4
    const int lbk = tid >> 5;        // 0..7
    const int lbn = (tid & 31) << 2; // 0..124

    const bool avalid = (row0 + lr) < M;
    int arow = row0 + lr;
    if (GATHER) {
        arow = avalid ? rowlist[arow] : 0;
        arow = (arow >= 0 && arow < Nn) ? arow : 0;   // defensive
    } else if (!avalid) arow = 0;

    auto aptr = [&](int k0) -> const float* {
        if (NSRC == 3) {
            const float* base = (k0 < 256) ? A0 : ((k0 < 512) ? A1 : A2);
            return base + (size_t)arow * 256 + (k0 & 255) + lk;
        }
        return A0 + (size_t)arow * lda + k0 + lk;
    };

    float4 av = avalid ? *(const float4*)aptr(0) : make_float4(0.f,0.f,0.f,0.f);
    const float* Bp = B + (size_t)lbk * ldb + col0 + lbn;
    float4 bv = *(const float4*)Bp;

    for (int k0 = 0; k0 < K; k0 += 8) {
        *(float2*)&As2[lk + 0][lr * 2] = make_float2(av.x, av.x);
        *(float2*)&As2[lk + 1][lr * 2] = make_float2(av.y, av.y);
        *(float2*)&As2[lk + 2][lr * 2] = make_float2(av.z, av.z);
        *(float2*)&As2[lk + 3][lr * 2] = make_float2(av.w, av.w);
        *(float4*)&Bs[lbk][lbn] = bv;
        __syncthreads();
        if (k0 + 8 < K) {      // prefetch next tile while computing this one
            av = avalid ? *(const float4*)aptr(k0 + 8) : make_float4(0.f,0.f,0.f,0.f);
            Bp += (size_t)8 * ldb;
            bv = *(const float4*)Bp;
        }
        #pragma unroll
        for (int k = 0; k < 8; k++) {
            unsigned long long a2[8], b2[4];
            ulonglong2 t0 = *(const ulonglong2*)&As2[k][ty * 16 + 0];
            ulonglong2 t1 = *(const ulonglong2*)&As2[k][ty * 16 + 4];
            ulonglong2 t2 = *(const ulonglong2*)&As2[k][ty * 16 + 8];
            ulonglong2 t3 = *(const ulonglong2*)&As2[k][ty * 16 + 12];
            a2[0] = t0.x; a2[1] = t0.y; a2[2] = t1.x; a2[3] = t1.y;
            a2[4] = t2.x; a2[5] = t2.y; a2[6] = t3.x; a2[7] = t3.y;
            ulonglong2 u0 = *(const ulonglong2*)&Bs[k][tx * 8];
            ulonglong2 u1 = *(const ulonglong2*)&Bs[k][tx * 8 + 4];
            b2[0] = u0.x; b2[1] = u0.y; b2[2] = u1.x; b2[3] = u1.y;
            #pragma unroll
            for (int i = 0; i < 8; i++)
                #pragma unroll
                for (int j = 0; j < 4; j++)
                    acc[i][j] = ffma2(a2[i], b2[j], acc[i][j]);
        }
        __syncthreads();
    }
}

__device__ __forceinline__ void unpack_acc(
    const unsigned long long (&acc)[8][4], float (&f)[8][8])
{
    #pragma unroll
    for (int i = 0; i < 8; i++)
        #pragma unroll
        for (int j = 0; j < 4; j++) {
            float2 v = *(const float2*)&acc[i][j];
            f[i][2 * j] = v.x; f[i][2 * j + 1] = v.y;
        }
}

// ---------------- generic GEMM with optional bias / add / relu ---------------
// ACT: 0 = none, 1 = relu.  NSRC=3 reads A as virtual [A0|A1|A2] concat.
template<int NSRC, int ACT, bool ADDMAT>
__global__ void __launch_bounds__(256, 2) k_gemm(
    const float* __restrict__ A0, const float* __restrict__ A1,
    const float* __restrict__ A2, const float* __restrict__ B,
    const float* __restrict__ bias, const float* __restrict__ addmat,
    float* __restrict__ C, int M, int K, int NC)
{
    unsigned long long acc[8][4];
    #pragma unroll
    for (int i = 0; i < 8; i++)
        #pragma unroll
        for (int j = 0; j < 4; j++) acc[i][j] = 0ull;

    gemm_core<NSRC, false>(A0, A1, A2, B, nullptr, M, K, K, NC, acc);

    float accf[8][8];
    unpack_acc(acc, accf);

    const int tid = threadIdx.x, tx = tid & 15, ty = tid >> 4;
    const int row0 = blockIdx.y * 128 + ty * 8;
    const int col0 = blockIdx.x * 128 + tx * 8;
    #pragma unroll
    for (int i = 0; i < 8; i++) {
        int r = row0 + i;
        if (r >= M) continue;
        #pragma unroll
        for (int jj = 0; jj < 8; jj += 4) {
            int c = col0 + jj;
            float4 v = *(float4*)&accf[i][jj];
            if (bias) {
                v.x += bias[c]; v.y += bias[c + 1]; v.z += bias[c + 2]; v.w += bias[c + 3];
            }
            if (ADDMAT) {
                float4 m = *(const float4*)&addmat[(size_t)r * NC + c];
                v.x += m.x; v.y += m.y; v.z += m.z; v.w += m.w;
            }
            if (ACT == 1) {
                v.x = fmaxf(v.x, 0.f); v.y = fmaxf(v.y, 0.f);
                v.z = fmaxf(v.z, 0.f); v.w = fmaxf(v.w, 0.f);
            }
            *(float4*)&C[(size_t)r * NC + c] = v;
        }
    }
}

// ---------------- gating head: logits -> softmax -> top2 -> routing lists ----
__global__ void k_gate(const float* __restrict__ Wg2, const float* __restrict__ bg2) {
    __shared__ int   scnt[NEx], sbase[NEx];
    __shared__ int   se[64];
    __shared__ int   snode[64];
    __shared__ int   spos[64];
    __shared__ float sg[64];

    const int tid = threadIdx.x;
    if (tid < NEx) scnt[tid] = 0;
    __syncthreads();

    const int warp = tid >> 5, lane = tid & 31;
    const int node = blockIdx.x * 32 + warp;

    if (node < Nn) {
        const float* gr = g_ghid + (size_t)node * GHd;
        float v0 = gr[lane], v1 = gr[lane + 32], v2 = gr[lane + 64], v3 = gr[lane + 96];
        float l[NEx];
        #pragma unroll
        for (int e = 0; e < NEx; e++) {
            float p = v0 * Wg2[lane * NEx + e]
                    + v1 * Wg2[(lane + 32) * NEx + e]
                    + v2 * Wg2[(lane + 64) * NEx + e]
                    + v3 * Wg2[(lane + 96) * NEx + e];
            #pragma unroll
            for (int off = 16; off > 0; off >>= 1)
                p += __shfl_xor_sync(0xffffffffu, p, off);
            l[e] = p;
        }
        if (lane == 0) {
            #pragma unroll
            for (int e = 0; e < NEx; e++) l[e] += bg2[e];
            int e0 = 0;
            #pragma unroll
            for (int e = 1; e < NEx; e++) if (l[e] > l[e0]) e0 = e;
            int e1 = -1;
            #pragma unroll
            for (int e = 0; e < NEx; e++)
                if (e != e0 && (e1 < 0 || l[e] > l[e1])) e1 = e;
            float gate0 = 1.f / (1.f + expf(l[e1] - l[e0]));
            float gate1 = 1.f - gate0;
            int s0 = warp * 2, s1 = warp * 2 + 1;
            se[s0] = e0; snode[s0] = node; sg[s0] = gate0;
            spos[s0] = atomicAdd(&scnt[e0], 1);
            se[s1] = e1; snode[s1] = node; sg[s1] = gate1;
            spos[s1] = atomicAdd(&scnt[e1], 1);
        }
    } else if (lane == 0) {
        se[warp * 2] = -1; se[warp * 2 + 1] = -1;
    }
    __syncthreads();
    if (tid < NEx) sbase[tid] = atomicAdd(&g_counts[tid], scnt[tid]);
    __syncthreads();
    if (tid < 64 && se[tid] >= 0) {
        int e = se[tid];
        int p = sbase[e] + spos[tid];
        if (p >= 0 && p < Nn) {
            g_lists[e * Nn + p] = snode[tid];
            g_gatew[e * Nn + p] = sg[tid];
        }
    }
}

// ---------------- expert layer 1: gathered rows, gelu ------------------------
__global__ void __launch_bounds__(256, 2) k_expert1(
    const float* __restrict__ text, const float* __restrict__ tab,
    const float* __restrict__ str,
    const float* __restrict__ We1, const float* __restrict__ be1)
{
    const int e = blockIdx.z;
    int M = g_counts[e];
    M = (M < Nn) ? M : Nn;
    if ((int)(blockIdx.y * 128) >= M) return;

    const float* xs[3] = { text, tab, str };
    const int map[NEx] = { 1, 2, 0, 0, 2 };   // xin = [tabular, structured, text, text, structured]
    const float* A = xs[map[e]];

    unsigned long long acc[8][4];
    #pragma unroll
    for (int i = 0; i < 8; i++)
        #pragma unroll
        for (int j = 0; j < 4; j++) acc[i][j] = 0ull;

    gemm_core<1, true>(A, nullptr, nullptr, We1 + (size_t)e * Ed * Hd,
                       g_lists + e * Nn, M, Ed, Ed, Hd, acc);

    float accf[8][8];
    unpack_acc(acc, accf);

    const float* bias = be1 + e * Hd;
    float* C = g_h1 + (size_t)e * Nn * Hd;
    const int tid = threadIdx.x, tx = tid & 15, ty = tid >> 4;
    const int row0 = blockIdx.y * 128 + ty * 8;
    const int col0 = blockIdx.x * 128 + tx * 8;
    #pragma unroll
    for (int i = 0; i < 8; i++) {
        int r = row0 + i;
        if (r >= M) continue;
        #pragma unroll
        for (int jj = 0; jj < 8; jj += 4) {
            int c = col0 + jj;
            float4 v;
            v.x = gelu_f(accf[i][jj + 0] + bias[c + 0]);
            v.y = gelu_f(accf[i][jj + 1] + bias[c + 1]);
            v.z = gelu_f(accf[i][jj + 2] + bias[c + 2]);
            v.w = gelu_f(accf[i][jj + 3] + bias[c + 3]);
            *(float4*)&C[(size_t)r * Hd + c] = v;
        }
    }
}

// ---------------- expert layer 2: scatter gate*out into node_feats -----------
__global__ void __launch_bounds__(256, 2) k_expert2(
    const float* __restrict__ We2, const float* __restrict__ be2)
{
    const int e = blockIdx.z;
    int M = g_counts[e];
    M = (M < Nn) ? M : Nn;
    if ((int)(blockIdx.y * 128) >= M) return;

    const float* A = g_h1 + (size_t)e * Nn * Hd;

    unsigned long long acc[8][4];
    #pragma unroll
    for (int i = 0; i < 8; i++)
        #pragma unroll
        for (int j = 0; j < 4; j++) acc[i][j] = 0ull;

    gemm_core<1, false>(A, nullptr, nullptr, We2 + (size_t)e * Hd * Hd,
                        nullptr, M, Hd, Hd, Hd, acc);

    float accf[8][8];
    unpack_acc(acc, accf);

    const float* bias = be2 + e * Hd;
    const int*   lst  = g_lists + e * Nn;
    const float* gw   = g_gatew + e * Nn;
    const int tid = threadIdx.x, tx = tid & 15, ty = tid >> 4;
    const int row0 = blockIdx.y * 128 + ty * 8;
    const int col0 = blockIdx.x * 128 + tx * 8;
    #pragma unroll
    for (int i = 0; i < 8; i++) {
        int r = row0 + i;
        if (r >= M) continue;
        int node = lst[r];
        if (node < 0 || node >= Nn) continue;   // defensive
        float g = gw[r];
        float* dst = g_nf + (size_t)node * Hd;
        #pragma unroll
        for (int jj = 0; jj < 8; jj += 4) {
            int c = col0 + jj;
            float4 v;
            v.x = g * (accf[i][jj + 0] + bias[c + 0]);
            v.y = g * (accf[i][jj + 1] + bias[c + 1]);
            v.z = g * (accf[i][jj + 2] + bias[c + 2]);
            v.w = g * (accf[i][jj + 3] + bias[c + 3]);
            atomicAdd((float4*)(dst + c), v);
        }
    }
}

// ---------------- edge segment-sum: msg[dst] += hw[src] ----------------------
__global__ void k_scatter(const int* __restrict__ ei, int nedges,
                          const float* __restrict__ hw, float* __restrict__ msg)
{
    int idx = blockIdx.x * blockDim.x + threadIdx.x;
    int eidx = idx >> 7;           // 128 threads per edge
    int t = idx & 127;
    if (eidx >= nedges) return;
    int s = ei[eidx];
    int d = ei[nedges + eidx];
    if ((unsigned)s >= (unsigned)Nn || (unsigned)d >= (unsigned)Nn) return;  // defensive
    float4 v = ((const float4*)(hw + (size_t)s * Hd))[t];
    atomicAdd((float4*)(msg + (size_t)d * Hd + (size_t)t * 4), v);
}

// ---------------- launch -----------------------------------------------------
extern "C" void kernel_launch(void* const* d_in, const int* in_sizes, int n_in,
                              void* d_out, int out_size)
{
    const float* text = (const float*)d_in[0];
    const float* tab  = (const float*)d_in[1];
    const float* str  = (const float*)d_in[2];
    const int*   ei   = (const int*)d_in[3];     // int32 edge index
    const float* Wg1  = (const float*)d_in[4];
    const float* bg1  = (const float*)d_in[5];
    const float* Wg2  = (const float*)d_in[6];
    const float* bg2  = (const float*)d_in[7];
    const float* We1  = (const float*)d_in[8];
    const float* be1  = (const float*)d_in[9];
    const float* We2  = (const float*)d_in[10];
    const float* be2  = (const float*)d_in[11];
    const float* Wself = (const float*)d_in[12];
    const float* Wnbr  = (const float*)d_in[13];
    float* out = (float*)d_out;
    const int nedges = in_sizes[3] / 2;

    void *pcnt, *pghid, *pnf, *phw, *pmsg, *phl;
    cudaGetSymbolAddress(&pcnt,  g_counts);
    cudaGetSymbolAddress(&pghid, g_ghid);
    cudaGetSymbolAddress(&pnf,   g_nf);
    cudaGetSymbolAddress(&phw,   g_hw);
    cudaGetSymbolAddress(&pmsg,  g_msg);
    cudaGetSymbolAddress(&phl,   g_hl);

    cudaMemsetAsync(pcnt, 0, sizeof(int) * NEx);
    cudaMemsetAsync(pnf,  0, sizeof(float) * (size_t)Nn * Hd);

    // 1) gating hidden: relu([text|tab|str] @ Wg1 + bg1)  (concat fused away)
    k_gemm<3, 1, false><<<dim3(GHd / 128, CDIV(Nn, 128)), 256>>>(
        text, tab, str, Wg1, bg1, nullptr, (float*)pghid, Nn, CC, GHd);

    // 2) gating head: softmax top-2, build routing lists
    k_gate<<<CDIV(Nn, 32), 1024>>>(Wg2, bg2);

    // 3) expert MLP layer 1 (gathered, gelu), all 5 experts in one launch
    k_expert1<<<dim3(Hd / 128, CDIV(Nn, 128), NEx), 256>>>(text, tab, str, We1, be1);

    // 4) expert MLP layer 2, scatter gate*out into node_feats
    k_expert2<<<dim3(Hd / 128, CDIV(Nn, 128), NEx), 256>>>(We2, be2);

    // ---- GNN layer 0 ----
    k_gemm<1, 0, false><<<dim3(Hd / 128, CDIV(Nn, 128)), 256>>>(
        (const float*)pnf, nullptr, nullptr, Wnbr, nullptr, nullptr,
        (float*)phw, Nn, Hd, Hd);
    cudaMemsetAsync(pmsg, 0, sizeof(float) * (size_t)Nn * Hd);
    k_scatter<<<CDIV(nedges * 128, 256), 256>>>(ei, nedges, (const float*)phw, (float*)pmsg);
    k_gemm<1, 1, true><<<dim3(Hd / 128, CDIV(Nn, 128)), 256>>>(
        (const float*)pnf, nullptr, nullptr, Wself, nullptr, (const float*)pmsg,
        (float*)phl, Nn, Hd, Hd);

    // ---- GNN layer 1 ----
    k_gemm<1, 0, false><<<dim3(Hd / 128, CDIV(Nn, 128)), 256>>>(
        (const float*)phl, nullptr, nullptr, Wnbr + (size_t)Hd * Hd, nullptr, nullptr,
        (float*)phw, Nn, Hd, Hd);
    cudaMemsetAsync(pmsg, 0, sizeof(float) * (size_t)Nn * Hd);
    k_scatter<<<CDIV(nedges * 128, 256), 256>>>(ei, nedges, (const float*)phw, (float*)pmsg);
    k_gemm<1, 1, true><<<dim3(Hd / 128, CDIV(Nn, 128)), 256>>>(
        (const float*)phl, nullptr, nullptr, Wself + (size_t)Hd * Hd, nullptr, (const float*)pmsg,
        out, Nn, Hd, Hd);
}

// round 4
// speedup vs baseline: 1.0979x; 1.0979x over previous
#include <cuda_runtime.h>
#include <cstdint>

#define CDIV(a,b) (((a)+(b)-1)/(b))

constexpr int Nn  = 50000;
constexpr int Ed  = 256;
constexpr int Hd  = 512;
constexpr int NEx = 5;
constexpr int GHd = 128;
constexpr int CC  = 768;   // 3*Ed

// ---------------- scratch (static device globals; no allocation) -------------
__device__ float g_ghid[(size_t)Nn * GHd];
__device__ int   g_lists[NEx * Nn];
__device__ float g_gatew[NEx * Nn];
__device__ int   g_counts[NEx];
__device__ float g_h1[(size_t)NEx * Nn * Hd];
__device__ float g_nf[(size_t)Nn * Hd];              // node_feats (h^0)
__device__ float g_msg[(size_t)Nn * Hd];             // segment-sum aggregate
__device__ float g_hl[(size_t)Nn * Hd];              // h after layer 0

// ---------------- helpers ----------------------------------------------------
__device__ __forceinline__ float gelu_f(float x) {
    float t = tanhf(0.7978845608028654f * (x + 0.044715f * x * x * x));
    return 0.5f * x * (1.0f + t);
}

// ---------------- SGEMM core: 128x128 tile, BK=8, 256 thr, 8x8/thread --------
// Double-buffered smem: one __syncthreads per k-tile.
// NSRC==3: A = virtual [A0|A1|A2], each Nn x 256.  NSRC==2: [A0|A1], each Nn x 512.
// BSPLIT: B rows 0..511 from B0, 512.. from B1 (both ldb wide).
template<int NSRC, bool GATHER, bool BSPLIT>
__device__ __forceinline__ void gemm_core(
    const float* __restrict__ A0, const float* __restrict__ A1,
    const float* __restrict__ A2,
    const float* __restrict__ B0, const float* __restrict__ B1,
    const int* __restrict__ rowlist, int M, int K, int lda, int ldb,
    float (&acc)[8][8])
{
    __shared__ float As[2][8][128];
    __shared__ float Bs[2][8][128];

    const int tid = threadIdx.x;
    const int tx = tid & 15, ty = tid >> 4;
    const int row0 = blockIdx.y * 128;
    const int col0 = blockIdx.x * 128;
    const int lr  = tid >> 1;        // 0..127
    const int lk  = (tid & 1) << 2;  // 0 or 4
    const int lbk = tid >> 5;        // 0..7
    const int lbn = (tid & 31) << 2; // 0..124

    const bool avalid = (row0 + lr) < M;
    int arow = row0 + lr;
    if (GATHER) {
        arow = avalid ? rowlist[arow] : 0;
        arow = (arow >= 0 && arow < Nn) ? arow : 0;   // defensive
    } else if (!avalid) arow = 0;

    auto aload = [&](int k0) -> float4 {
        if (!avalid) return make_float4(0.f, 0.f, 0.f, 0.f);
        const float* p;
        if (NSRC == 3) {
            const float* base = (k0 < 256) ? A0 : ((k0 < 512) ? A1 : A2);
            p = base + (size_t)arow * 256 + (k0 & 255) + lk;
        } else if (NSRC == 2) {
            const float* base = (k0 < 512) ? A0 : A1;
            p = base + (size_t)arow * 512 + (k0 & 511) + lk;
        } else {
            p = A0 + (size_t)arow * lda + k0 + lk;
        }
        return *(const float4*)p;
    };
    auto bload = [&](int k0) -> float4 {
        int kr = k0 + lbk;
        const float* p;
        if (BSPLIT) p = (kr < 512) ? (B0 + (size_t)kr * ldb)
                                   : (B1 + (size_t)(kr - 512) * ldb);
        else        p = B0 + (size_t)kr * ldb;
        return *(const float4*)(p + col0 + lbn);
    };

    float4 av = aload(0);
    float4 bv = bload(0);
    As[0][lk + 0][lr] = av.x; As[0][lk + 1][lr] = av.y;
    As[0][lk + 2][lr] = av.z; As[0][lk + 3][lr] = av.w;
    *(float4*)&Bs[0][lbk][lbn] = bv;
    __syncthreads();

    int p = 0;
    for (int k0 = 0; k0 < K; k0 += 8) {
        const bool more = (k0 + 8) < K;
        if (more) { av = aload(k0 + 8); bv = bload(k0 + 8); }   // gmem prefetch
        #pragma unroll
        for (int k = 0; k < 8; k++) {
            float a[8], b[8];
            *(float4*)(a)     = *(const float4*)&As[p][k][ty * 8];
            *(float4*)(a + 4) = *(const float4*)&As[p][k][ty * 8 + 4];
            *(float4*)(b)     = *(const float4*)&Bs[p][k][tx * 8];
            *(float4*)(b + 4) = *(const float4*)&Bs[p][k][tx * 8 + 4];
            #pragma unroll
            for (int i = 0; i < 8; i++)
                #pragma unroll
                for (int j = 0; j < 8; j++)
                    acc[i][j] = fmaf(a[i], b[j], acc[i][j]);
        }
        if (more) {
            const int q = p ^ 1;
            As[q][lk + 0][lr] = av.x; As[q][lk + 1][lr] = av.y;
            As[q][lk + 2][lr] = av.z; As[q][lk + 3][lr] = av.w;
            *(float4*)&Bs[q][lbk][lbn] = bv;
            __syncthreads();
            p = q;
        }
    }
}

// ---------------- generic GEMM with optional bias / relu ---------------------
// ACT: 0 = none, 1 = relu
template<int NSRC, int ACT, bool BSPLIT>
__global__ void __launch_bounds__(256, 2) k_gemm(
    const float* __restrict__ A0, const float* __restrict__ A1,
    const float* __restrict__ A2,
    const float* __restrict__ B0, const float* __restrict__ B1,
    const float* __restrict__ bias,
    float* __restrict__ C, int M, int K, int NC)
{
    float acc[8][8];
    #pragma unroll
    for (int i = 0; i < 8; i++)
        #pragma unroll
        for (int j = 0; j < 8; j++) acc[i][j] = 0.f;

    gemm_core<NSRC, false, BSPLIT>(A0, A1, A2, B0, B1, nullptr, M, K, K, NC, acc);

    const int tid = threadIdx.x, tx = tid & 15, ty = tid >> 4;
    const int row0 = blockIdx.y * 128 + ty * 8;
    const int col0 = blockIdx.x * 128 + tx * 8;
    #pragma unroll
    for (int i = 0; i < 8; i++) {
        int r = row0 + i;
        if (r >= M) continue;
        #pragma unroll
        for (int jj = 0; jj < 8; jj += 4) {
            int c = col0 + jj;
            float4 v = *(float4*)&acc[i][jj];
            if (bias) {
                v.x += bias[c]; v.y += bias[c + 1]; v.z += bias[c + 2]; v.w += bias[c + 3];
            }
            if (ACT == 1) {
                v.x = fmaxf(v.x, 0.f); v.y = fmaxf(v.y, 0.f);
                v.z = fmaxf(v.z, 0.f); v.w = fmaxf(v.w, 0.f);
            }
            *(float4*)&C[(size_t)r * NC + c] = v;
        }
    }
}

// ---------------- gating head: logits -> softmax -> top2 -> routing lists ----
__global__ void k_gate(const float* __restrict__ Wg2, const float* __restrict__ bg2) {
    __shared__ int   scnt[NEx], sbase[NEx];
    __shared__ int   se[64];
    __shared__ int   snode[64];
    __shared__ int   spos[64];
    __shared__ float sg[64];

    const int tid = threadIdx.x;
    if (tid < NEx) scnt[tid] = 0;
    __syncthreads();

    const int warp = tid >> 5, lane = tid & 31;
    const int node = blockIdx.x * 32 + warp;

    if (node < Nn) {
        const float* gr = g_ghid + (size_t)node * GHd;
        float v0 = gr[lane], v1 = gr[lane + 32], v2 = gr[lane + 64], v3 = gr[lane + 96];
        float l[NEx];
        #pragma unroll
        for (int e = 0; e < NEx; e++) {
            float p = v0 * Wg2[lane * NEx + e]
                    + v1 * Wg2[(lane + 32) * NEx + e]
                    + v2 * Wg2[(lane + 64) * NEx + e]
                    + v3 * Wg2[(lane + 96) * NEx + e];
            #pragma unroll
            for (int off = 16; off > 0; off >>= 1)
                p += __shfl_xor_sync(0xffffffffu, p, off);
            l[e] = p;
        }
        if (lane == 0) {
            #pragma unroll
            for (int e = 0; e < NEx; e++) l[e] += bg2[e];
            int e0 = 0;
            #pragma unroll
            for (int e = 1; e < NEx; e++) if (l[e] > l[e0]) e0 = e;
            int e1 = -1;
            #pragma unroll
            for (int e = 0; e < NEx; e++)
                if (e != e0 && (e1 < 0 || l[e] > l[e1])) e1 = e;
            float gate0 = 1.f / (1.f + expf(l[e1] - l[e0]));
            float gate1 = 1.f - gate0;
            int s0 = warp * 2, s1 = warp * 2 + 1;
            se[s0] = e0; snode[s0] = node; sg[s0] = gate0;
            spos[s0] = atomicAdd(&scnt[e0], 1);
            se[s1] = e1; snode[s1] = node; sg[s1] = gate1;
            spos[s1] = atomicAdd(&scnt[e1], 1);
        }
    } else if (lane == 0) {
        se[warp * 2] = -1; se[warp * 2 + 1] = -1;
    }
    __syncthreads();
    if (tid < NEx) sbase[tid] = atomicAdd(&g_counts[tid], scnt[tid]);
    __syncthreads();
    if (tid < 64 && se[tid] >= 0) {
        int e = se[tid];
        int p = sbase[e] + spos[tid];
        if (p >= 0 && p < Nn) {
            g_lists[e * Nn + p] = snode[tid];
            g_gatew[e * Nn + p] = sg[tid];
        }
    }
}

// ---------------- expert layer 1: gathered rows, gelu ------------------------
__global__ void __launch_bounds__(256, 2) k_expert1(
    const float* __restrict__ text, const float* __restrict__ tab,
    const float* __restrict__ str,
    const float* __restrict__ We1, const float* __restrict__ be1)
{
    const int e = blockIdx.z;
    int M = g_counts[e];
    M = (M < Nn) ? M : Nn;
    if ((int)(blockIdx.y * 128) >= M) return;

    const float* xs[3] = { text, tab, str };
    const int map[NEx] = { 1, 2, 0, 0, 2 };   // xin = [tabular, structured, text, text, structured]
    const float* A = xs[map[e]];

    float acc[8][8];
    #pragma unroll
    for (int i = 0; i < 8; i++)
        #pragma unroll
        for (int j = 0; j < 8; j++) acc[i][j] = 0.f;

    gemm_core<1, true, false>(A, nullptr, nullptr, We1 + (size_t)e * Ed * Hd, nullptr,
                              g_lists + e * Nn, M, Ed, Ed, Hd, acc);

    const float* bias = be1 + e * Hd;
    float* C = g_h1 + (size_t)e * Nn * Hd;
    const int tid = threadIdx.x, tx = tid & 15, ty = tid >> 4;
    const int row0 = blockIdx.y * 128 + ty * 8;
    const int col0 = blockIdx.x * 128 + tx * 8;
    #pragma unroll
    for (int i = 0; i < 8; i++) {
        int r = row0 + i;
        if (r >= M) continue;
        #pragma unroll
        for (int jj = 0; jj < 8; jj += 4) {
            int c = col0 + jj;
            float4 v;
            v.x = gelu_f(acc[i][jj + 0] + bias[c + 0]);
            v.y = gelu_f(acc[i][jj + 1] + bias[c + 1]);
            v.z = gelu_f(acc[i][jj + 2] + bias[c + 2]);
            v.w = gelu_f(acc[i][jj + 3] + bias[c + 3]);
            *(float4*)&C[(size_t)r * Hd + c] = v;
        }
    }
}

// ---------------- expert layer 2: scatter gate*out into node_feats -----------
__global__ void __launch_bounds__(256, 2) k_expert2(
    const float* __restrict__ We2, const float* __restrict__ be2)
{
    const int e = blockIdx.z;
    int M = g_counts[e];
    M = (M < Nn) ? M : Nn;
    if ((int)(blockIdx.y * 128) >= M) return;

    const float* A = g_h1 + (size_t)e * Nn * Hd;

    float acc[8][8];
    #pragma unroll
    for (int i = 0; i < 8; i++)
        #pragma unroll
        for (int j = 0; j < 8; j++) acc[i][j] = 0.f;

    gemm_core<1, false, false>(A, nullptr, nullptr, We2 + (size_t)e * Hd * Hd, nullptr,
                               nullptr, M, Hd, Hd, Hd, acc);

    const float* bias = be2 + e * Hd;
    const int*   lst  = g_lists + e * Nn;
    const float* gw   = g_gatew + e * Nn;
    const int tid = threadIdx.x, tx = tid & 15, ty = tid >> 4;
    const int row0 = blockIdx.y * 128 + ty * 8;
    const int col0 = blockIdx.x * 128 + tx * 8;
    #pragma unroll
    for (int i = 0; i < 8; i++) {
        int r = row0 + i;
        if (r >= M) continue;
        int node = lst[r];
        if (node < 0 || node >= Nn) continue;   // defensive
        float g = gw[r];
        float* dst = g_nf + (size_t)node * Hd;
        #pragma unroll
        for (int jj = 0; jj < 8; jj += 4) {
            int c = col0 + jj;
            float4 v;
            v.x = g * (acc[i][jj + 0] + bias[c + 0]);
            v.y = g * (acc[i][jj + 1] + bias[c + 1]);
            v.z = g * (acc[i][jj + 2] + bias[c + 2]);
            v.w = g * (acc[i][jj + 3] + bias[c + 3]);
            atomicAdd((float4*)(dst + c), v);
        }
    }
}

// ---------------- edge segment-sum: agg[dst] += h[src] -----------------------
__global__ void k_scatter(const int* __restrict__ ei, int nedges,
                          const float* __restrict__ h, float* __restrict__ agg)
{
    int idx = blockIdx.x * blockDim.x + threadIdx.x;
    int eidx = idx >> 7;           // 128 threads per edge
    int t = idx & 127;
    if (eidx >= nedges) return;
    int s = ei[eidx];
    int d = ei[nedges + eidx];
    if ((unsigned)s >= (unsigned)Nn || (unsigned)d >= (unsigned)Nn) return;  // defensive
    float4 v = ((const float4*)(h + (size_t)s * Hd))[t];
    atomicAdd((float4*)(agg + (size_t)d * Hd + (size_t)t * 4), v);
}

// ---------------- launch -----------------------------------------------------
extern "C" void kernel_launch(void* const* d_in, const int* in_sizes, int n_in,
                              void* d_out, int out_size)
{
    const float* text = (const float*)d_in[0];
    const float* tab  = (const float*)d_in[1];
    const float* str  = (const float*)d_in[2];
    const int*   ei   = (const int*)d_in[3];     // int32 edge index
    const float* Wg1  = (const float*)d_in[4];
    const float* bg1  = (const float*)d_in[5];
    const float* Wg2  = (const float*)d_in[6];
    const float* bg2  = (const float*)d_in[7];
    const float* We1  = (const float*)d_in[8];
    const float* be1  = (const float*)d_in[9];
    const float* We2  = (const float*)d_in[10];
    const float* be2  = (const float*)d_in[11];
    const float* Wself = (const float*)d_in[12];
    const float* Wnbr  = (const float*)d_in[13];
    float* out = (float*)d_out;
    const int nedges = in_sizes[3] / 2;

    void *pcnt, *pghid, *pnf, *pmsg, *phl;
    cudaGetSymbolAddress(&pcnt,  g_counts);
    cudaGetSymbolAddress(&pghid, g_ghid);
    cudaGetSymbolAddress(&pnf,   g_nf);
    cudaGetSymbolAddress(&pmsg,  g_msg);
    cudaGetSymbolAddress(&phl,   g_hl);

    cudaMemsetAsync(pcnt, 0, sizeof(int) * NEx);
    cudaMemsetAsync(pnf,  0, sizeof(float) * (size_t)Nn * Hd);

    // 1) gating hidden: relu([text|tab|str] @ Wg1 + bg1)  (concat fused away)
    k_gemm<3, 1, false><<<dim3(GHd / 128, CDIV(Nn, 128)), 256>>>(
        text, tab, str, Wg1, nullptr, bg1, (float*)pghid, Nn, CC, GHd);

    // 2) gating head: softmax top-2, build routing lists
    k_gate<<<CDIV(Nn, 32), 1024>>>(Wg2, bg2);

    // 3) expert MLP layer 1 (gathered, gelu), all 5 experts in one launch
    k_expert1<<<dim3(Hd / 128, CDIV(Nn, 128), NEx), 256>>>(text, tab, str, We1, be1);

    // 4) expert MLP layer 2, scatter gate*out into node_feats
    k_expert2<<<dim3(Hd / 128, CDIV(Nn, 128), NEx), 256>>>(We2, be2);

    // ---- GNN layer 0:  h1 = relu(h @ Wself0 + segsum(h[src]) @ Wnbr0) ----
    // (segment_sum commutes with the linear map: scatter h first, then one
    //  fused K=1024 GEMM over the virtual concat [h | agg] @ [[Wself],[Wnbr]])
    cudaMemsetAsync(pmsg, 0, sizeof(float) * (size_t)Nn * Hd);
    k_scatter<<<CDIV(nedges * 128, 256), 256>>>(ei, nedges, (const float*)pnf, (float*)pmsg);
    k_gemm<2, 1, true><<<dim3(Hd / 128, CDIV(Nn, 128)), 256>>>(
        (const float*)pnf, (const float*)pmsg, nullptr,
        Wself, Wnbr, nullptr, (float*)phl, Nn, 2 * Hd, Hd);

    // ---- GNN layer 1 ----
    cudaMemsetAsync(pmsg, 0, sizeof(float) * (size_t)Nn * Hd);
    k_scatter<<<CDIV(nedges * 128, 256), 256>>>(ei, nedges, (const float*)phl, (float*)pmsg);
    k_gemm<2, 1, true><<<dim3(Hd / 128, CDIV(Nn, 128)), 256>>>(
        (const float*)phl, (const float*)pmsg, nullptr,
        Wself + (size_t)Hd * Hd, Wnbr + (size_t)Hd * Hd, nullptr,
        out, Nn, 2 * Hd, Hd);
}

// round 6
// speedup vs baseline: 1.7722x; 1.6141x over previous
#include <cuda_runtime.h>
#include <cuda_bf16.h>
#include <cstdint>

#define CDIV(a,b) (((a)+(b)-1)/(b))

constexpr int Nn  = 50000;
constexpr int Ed  = 256;
constexpr int Hd  = 512;
constexpr int NEx = 5;
constexpr int GHd = 128;

// ---------------- scratch (static device globals; no allocation) -------------
__device__ float g_ghid[(size_t)Nn * GHd];
__device__ int   g_lists[NEx * Nn];
__device__ float g_gatew[NEx * Nn];
__device__ int   g_counts[NEx];
__device__ float g_h1[(size_t)NEx * Nn * Hd];
__device__ float g_nf[(size_t)Nn * Hd];
__device__ float g_msg[(size_t)Nn * Hd];
__device__ float g_hl[(size_t)Nn * Hd];

// ---------------- helpers ----------------------------------------------------
__device__ __forceinline__ float gelu_f(float x) {
    float t = tanhf(0.7978845608028654f * (x + 0.044715f * x * x * x));
    return 0.5f * x * (1.0f + t);
}

// pack two floats into bf16x2 (lo -> low half), rn
__device__ __forceinline__ uint32_t packbf(float lo, float hi) {
    __nv_bfloat162 h = __floats2bfloat162_rn(lo, hi);
    return *reinterpret_cast<uint32_t*>(&h);
}
__device__ __forceinline__ float bfround(float x) {
    return __bfloat162float(__float2bfloat16(x));
}

__device__ __forceinline__ void mma16816(
    float (&c)[4], const uint32_t (&a)[4], const uint32_t (&b)[2])
{
    asm volatile(
        "mma.sync.aligned.m16n8k16.row.col.f32.bf16.bf16.f32 "
        "{%0,%1,%2,%3}, {%4,%5,%6,%7}, {%8,%9}, {%0,%1,%2,%3};"
        : "+f"(c[0]), "+f"(c[1]), "+f"(c[2]), "+f"(c[3])
        : "r"(a[0]), "r"(a[1]), "r"(a[2]), "r"(a[3]), "r"(b[0]), "r"(b[1]));
}

__device__ __forceinline__ void red2(float* p, float x, float y) {
    asm volatile("red.global.add.v2.f32 [%0], {%1,%2};"
                 :: "l"(p), "f"(x), "f"(y) : "memory");
}

// ---------------- bf16x3 tensor-core GEMM (128x128 tile, BK=32) --------------
// 256 thr = 8 warps (2 x 4), warp tile 64x32, mma m16n8k16, 3-pass hi/lo split.
// NSRC==3: A = virtual [A0|A1|A2] (each Nn x 256). NSRC==2: [A0|A1] (each Nn x 512).
// ESEL: per-expert input select.  AEXP: A0 += e*Nn*K.  GATHER: rows via rowlist.
// BSPLIT: B rows <512 from B0 else B1.  ACT: 0 none, 1 relu, 2 gelu.
// SCATTER: gate-weighted atomic into C[node].  EXPERT: per-expert via blockIdx.z.
template<int NSRC, bool ESEL, bool AEXP, bool GATHER, bool BSPLIT,
         int ACT, bool SCATTER, bool EXPERT>
__global__ void __launch_bounds__(256) k_mma(
    const float* __restrict__ A0, const float* __restrict__ A1,
    const float* __restrict__ A2,
    const float* __restrict__ B0, const float* __restrict__ B1,
    const float* __restrict__ bias, float* __restrict__ C,
    const int* __restrict__ rowlist, const float* __restrict__ gatew,
    int Mfixed, int K, int NC)
{
    int M;
    const float* Bp    = B0;
    const float* biasp = bias;
    float*       Cp    = C;
    const int*   rl    = rowlist;
    const float* gwp   = gatew;
    const float* Asel  = A0;
    if (EXPERT) {
        int e = blockIdx.z;
        M = g_counts[e]; if (M > Nn) M = Nn;
        Bp = B0 + (size_t)e * (size_t)K * NC;
        if (bias) biasp = bias + (size_t)e * NC;
        if (ESEL) {
            const int map[NEx] = { 1, 2, 0, 0, 2 };  // tab, str, text, text, str
            int s = map[e];
            Asel = (s == 0) ? A0 : ((s == 1) ? A1 : A2);
        }
        if (AEXP) Asel = A0 + (size_t)e * (size_t)Nn * K;
        rl  = rowlist + e * Nn;
        gwp = gatew   + e * Nn;
        if (!SCATTER) Cp = C + (size_t)e * (size_t)Nn * NC;
    } else {
        M = Mfixed;
    }
    if ((int)(blockIdx.y * 128) >= M) return;

    // [hi/lo][outer 128][k 32 + pad 8]
    __shared__ __nv_bfloat16 sA[2][128][40];
    __shared__ __nv_bfloat16 sB[2][128][40];

    const int tid  = threadIdx.x;
    const int warp = tid >> 5, lane = tid & 31;
    const int wm = warp >> 2, wn = warp & 3;      // warp tile: 64 x 32
    const int gid = lane >> 2, tig = lane & 3;
    const int row0 = blockIdx.y * 128;
    const int col0 = blockIdx.x * 128;

    // ---- A-side loader: thread handles row am, 16 k-values at ak ----
    const int am = tid >> 1;
    const int ak = (tid & 1) << 4;
    const bool avalid = (row0 + am) < M;
    int arow = row0 + am;
    if (GATHER) {
        arow = avalid ? rl[arow] : 0;
        if ((unsigned)arow >= (unsigned)Nn) arow = 0;
    } else if (!avalid) arow = 0;

    auto aload = [&](int k0, float4 (&d)[4]) {
        if (!avalid) {
            d[0] = d[1] = d[2] = d[3] = make_float4(0.f, 0.f, 0.f, 0.f);
            return;
        }
        int kg = k0 + ak;
        const float* p;
        if (NSRC == 3) {
            const float* s = (kg < 256) ? A0 : ((kg < 512) ? A1 : A2);
            p = s + (size_t)arow * 256 + (kg & 255);
        } else if (NSRC == 2) {
            const float* s = (kg < 512) ? A0 : A1;
            p = s + (size_t)arow * 512 + (kg & 511);
        } else {
            p = Asel + (size_t)arow * (size_t)K + kg;
        }
        #pragma unroll
        for (int q = 0; q < 4; q++) d[q] = *(const float4*)(p + q * 4);
    };

    // ---- B-side loader: thread handles out-col bn, 16 k-values at bk ----
    const int bn = tid >> 1;
    const int bk = (tid & 1) << 4;
    auto bload = [&](int k0, float (&d)[16]) {
        #pragma unroll
        for (int j = 0; j < 16; j++) {
            int kr = k0 + bk + j;
            const float* p;
            if (BSPLIT) p = (kr < 512) ? (B0 + (size_t)kr * NC)
                                       : (B1 + (size_t)(kr - 512) * NC);
            else        p = Bp + (size_t)kr * NC;
            d[j] = p[col0 + bn];
        }
    };

    float c[4][4][4];   // [mi][nj][frag]
    #pragma unroll
    for (int i = 0; i < 4; i++)
        #pragma unroll
        for (int j = 0; j < 4; j++)
            #pragma unroll
            for (int q = 0; q < 4; q++) c[i][j][q] = 0.f;

    const int nch = K >> 5;
    float4 apre[4]; float bpre[16];
    aload(0, apre); bload(0, bpre);

    for (int ch = 0; ch < nch; ch++) {
        // ---- stage to smem with hi/lo split ----
        #pragma unroll
        for (int q = 0; q < 4; q++) {
            float4 v = apre[q];
            float hx = bfround(v.x), hy = bfround(v.y);
            float hz = bfround(v.z), hw = bfround(v.w);
            *(uint32_t*)&sA[0][am][ak + q * 4]     = packbf(v.x, v.y);
            *(uint32_t*)&sA[0][am][ak + q * 4 + 2] = packbf(v.z, v.w);
            *(uint32_t*)&sA[1][am][ak + q * 4]     = packbf(v.x - hx, v.y - hy);
            *(uint32_t*)&sA[1][am][ak + q * 4 + 2] = packbf(v.z - hz, v.w - hw);
        }
        #pragma unroll
        for (int j = 0; j < 16; j += 2) {
            float x = bpre[j], y = bpre[j + 1];
            float hx = bfround(x), hy = bfround(y);
            *(uint32_t*)&sB[0][bn][bk + j] = packbf(x, y);
            *(uint32_t*)&sB[1][bn][bk + j] = packbf(x - hx, y - hy);
        }
        __syncthreads();

        if (ch + 1 < nch) { aload((ch + 1) << 5, apre); bload((ch + 1) << 5, bpre); }

        // ---- compute: 2 k16-steps ----
        #pragma unroll
        for (int ks = 0; ks < 32; ks += 16) {
            uint32_t bh[4][2], bl[4][2];
            #pragma unroll
            for (int nj = 0; nj < 4; nj++) {
                int cB = wn * 32 + nj * 8 + gid;
                bh[nj][0] = *(const uint32_t*)&sB[0][cB][ks + tig * 2];
                bh[nj][1] = *(const uint32_t*)&sB[0][cB][ks + tig * 2 + 8];
                bl[nj][0] = *(const uint32_t*)&sB[1][cB][ks + tig * 2];
                bl[nj][1] = *(const uint32_t*)&sB[1][cB][ks + tig * 2 + 8];
            }
            #pragma unroll
            for (int mi = 0; mi < 4; mi++) {
                int rA = wm * 64 + mi * 16 + gid;
                uint32_t ah[4], al[4];
                ah[0] = *(const uint32_t*)&sA[0][rA][ks + tig * 2];
                ah[1] = *(const uint32_t*)&sA[0][rA + 8][ks + tig * 2];
                ah[2] = *(const uint32_t*)&sA[0][rA][ks + tig * 2 + 8];
                ah[3] = *(const uint32_t*)&sA[0][rA + 8][ks + tig * 2 + 8];
                al[0] = *(const uint32_t*)&sA[1][rA][ks + tig * 2];
                al[1] = *(const uint32_t*)&sA[1][rA + 8][ks + tig * 2];
                al[2] = *(const uint32_t*)&sA[1][rA][ks + tig * 2 + 8];
                al[3] = *(const uint32_t*)&sA[1][rA + 8][ks + tig * 2 + 8];
                #pragma unroll
                for (int nj = 0; nj < 4; nj++) {
                    mma16816(c[mi][nj], ah, bh[nj]);   // Ah*Bh
                    mma16816(c[mi][nj], ah, bl[nj]);   // Ah*Bl
                    mma16816(c[mi][nj], al, bh[nj]);   // Al*Bh
                }
            }
        }
        __syncthreads();
    }

    // ---- epilogue ----
    #pragma unroll
    for (int mi = 0; mi < 4; mi++) {
        #pragma unroll
        for (int h = 0; h < 2; h++) {
            int rg = row0 + wm * 64 + mi * 16 + gid + h * 8;
            if (rg >= M) continue;
            int   node = 0;
            float gw   = 0.f;
            float* dst = nullptr;
            if (SCATTER) {
                node = rl[rg];
                gw   = gwp[rg];
                if ((unsigned)node < (unsigned)Nn) dst = Cp + (size_t)node * NC;
            }
            #pragma unroll
            for (int nj = 0; nj < 4; nj++) {
                int col = col0 + wn * 32 + nj * 8 + tig * 2;
                float vx = c[mi][nj][h * 2 + 0];
                float vy = c[mi][nj][h * 2 + 1];
                if (biasp) { vx += biasp[col]; vy += biasp[col + 1]; }
                if (ACT == 1) { vx = fmaxf(vx, 0.f); vy = fmaxf(vy, 0.f); }
                else if (ACT == 2) { vx = gelu_f(vx); vy = gelu_f(vy); }
                if (SCATTER) {
                    if (dst) red2(dst + col, gw * vx, gw * vy);
                } else {
                    *(float2*)(Cp + (size_t)rg * NC + col) = make_float2(vx, vy);
                }
            }
        }
    }
}

// ---------------- gating head: logits -> softmax -> top2 -> routing lists ----
__global__ void k_gate(const float* __restrict__ Wg2, const float* __restrict__ bg2) {
    __shared__ int   scnt[NEx], sbase[NEx];
    __shared__ int   se[64];
    __shared__ int   snode[64];
    __shared__ int   spos[64];
    __shared__ float sg[64];

    const int tid = threadIdx.x;
    if (tid < NEx) scnt[tid] = 0;
    __syncthreads();

    const int warp = tid >> 5, lane = tid & 31;
    const int node = blockIdx.x * 32 + warp;

    if (node < Nn) {
        const float* gr = g_ghid + (size_t)node * GHd;
        float v0 = gr[lane], v1 = gr[lane + 32], v2 = gr[lane + 64], v3 = gr[lane + 96];
        float l[NEx];
        #pragma unroll
        for (int e = 0; e < NEx; e++) {
            float p = v0 * Wg2[lane * NEx + e]
                    + v1 * Wg2[(lane + 32) * NEx + e]
                    + v2 * Wg2[(lane + 64) * NEx + e]
                    + v3 * Wg2[(lane + 96) * NEx + e];
            #pragma unroll
            for (int off = 16; off > 0; off >>= 1)
                p += __shfl_xor_sync(0xffffffffu, p, off);
            l[e] = p;
        }
        if (lane == 0) {
            #pragma unroll
            for (int e = 0; e < NEx; e++) l[e] += bg2[e];
            int e0 = 0;
            #pragma unroll
            for (int e = 1; e < NEx; e++) if (l[e] > l[e0]) e0 = e;
            int e1 = -1;
            #pragma unroll
            for (int e = 0; e < NEx; e++)
                if (e != e0 && (e1 < 0 || l[e] > l[e1])) e1 = e;
            float gate0 = 1.f / (1.f + expf(l[e1] - l[e0]));
            float gate1 = 1.f - gate0;
            int s0 = warp * 2, s1 = warp * 2 + 1;
            se[s0] = e0; snode[s0] = node; sg[s0] = gate0;
            spos[s0] = atomicAdd(&scnt[e0], 1);
            se[s1] = e1; snode[s1] = node; sg[s1] = gate1;
            spos[s1] = atomicAdd(&scnt[e1], 1);
        }
    } else if (lane == 0) {
        se[warp * 2] = -1; se[warp * 2 + 1] = -1;
    }
    __syncthreads();
    if (tid < NEx) sbase[tid] = atomicAdd(&g_counts[tid], scnt[tid]);
    __syncthreads();
    if (tid < 64 && se[tid] >= 0) {
        int e = se[tid];
        int p = sbase[e] + spos[tid];
        if (p >= 0 && p < Nn) {
            g_lists[e * Nn + p] = snode[tid];
            g_gatew[e * Nn + p] = sg[tid];
        }
    }
}

// ---------------- edge segment-sum: agg[dst] += h[src] -----------------------
__global__ void k_scatter(const int* __restrict__ ei, int nedges,
                          const float* __restrict__ h, float* __restrict__ agg)
{
    int idx = blockIdx.x * blockDim.x + threadIdx.x;
    int eidx = idx >> 7;           // 128 threads per edge
    int t = idx & 127;
    if (eidx >= nedges) return;
    int s = ei[eidx];
    int d = ei[nedges + eidx];
    if ((unsigned)s >= (unsigned)Nn || (unsigned)d >= (unsigned)Nn) return;
    float4 v = ((const float4*)(h + (size_t)s * Hd))[t];
    atomicAdd((float4*)(agg + (size_t)d * Hd + (size_t)t * 4), v);
}

// ---------------- launch -----------------------------------------------------
extern "C" void kernel_launch(void* const* d_in, const int* in_sizes, int n_in,
                              void* d_out, int out_size)
{
    const float* text = (const float*)d_in[0];
    const float* tab  = (const float*)d_in[1];
    const float* str  = (const float*)d_in[2];
    const int*   ei   = (const int*)d_in[3];     // int32 edge index
    const float* Wg1  = (const float*)d_in[4];
    const float* bg1  = (const float*)d_in[5];
    const float* Wg2  = (const float*)d_in[6];
    const float* bg2  = (const float*)d_in[7];
    const float* We1  = (const float*)d_in[8];
    const float* be1  = (const float*)d_in[9];
    const float* We2  = (const float*)d_in[10];
    const float* be2  = (const float*)d_in[11];
    const float* Wself = (const float*)d_in[12];
    const float* Wnbr  = (const float*)d_in[13];
    float* out = (float*)d_out;
    const int nedges = in_sizes[3] / 2;

    void *pcnt, *pghid, *pnf, *pmsg, *phl, *ph1, *plists, *pgatew;
    cudaGetSymbolAddress(&pcnt,   g_counts);
    cudaGetSymbolAddress(&pghid,  g_ghid);
    cudaGetSymbolAddress(&pnf,    g_nf);
    cudaGetSymbolAddress(&pmsg,   g_msg);
    cudaGetSymbolAddress(&phl,    g_hl);
    cudaGetSymbolAddress(&ph1,    g_h1);
    cudaGetSymbolAddress(&plists, g_lists);
    cudaGetSymbolAddress(&pgatew, g_gatew);

    cudaMemsetAsync(pcnt, 0, sizeof(int) * NEx);
    cudaMemsetAsync(pnf,  0, sizeof(float) * (size_t)Nn * Hd);

    const int MT = CDIV(Nn, 128);   // 391 M-tiles

    // 1) gating hidden: relu([text|tab|str] @ Wg1 + bg1)
    k_mma<3, false, false, false, false, 1, false, false>
        <<<dim3(1, MT), 256>>>(
        text, tab, str, Wg1, nullptr, bg1, (float*)pghid,
        nullptr, nullptr, Nn, 3 * Ed, GHd);

    // 2) gating head: softmax top-2, build routing lists
    k_gate<<<CDIV(Nn, 32), 1024>>>(Wg2, bg2);

    // 3) expert MLP layer 1 (gathered rows, gelu), all 5 experts in one launch
    k_mma<1, true, false, true, false, 2, false, true>
        <<<dim3(Hd / 128, MT, NEx), 256>>>(
        text, tab, str, We1, nullptr, be1, (float*)ph1,
        (const int*)plists, (const float*)pgatew, 0, Ed, Hd);

    // 4) expert MLP layer 2, scatter gate*out into node_feats
    k_mma<1, false, true, false, false, 0, true, true>
        <<<dim3(Hd / 128, MT, NEx), 256>>>(
        (const float*)ph1, nullptr, nullptr, We2, nullptr, be2, (float*)pnf,
        (const int*)plists, (const float*)pgatew, 0, Hd, Hd);

    // ---- GNN layer 0: h1 = relu([h | segsum(h)] @ [[Wself0],[Wnbr0]]) ----
    cudaMemsetAsync(pmsg, 0, sizeof(float) * (size_t)Nn * Hd);
    k_scatter<<<CDIV(nedges * 128, 256), 256>>>(ei, nedges, (const float*)pnf, (float*)pmsg);
    k_mma<2, false, false, false, true, 1, false, false>
        <<<dim3(Hd / 128, MT), 256>>>(
        (const float*)pnf, (const float*)pmsg, nullptr, Wself, Wnbr,
        nullptr, (float*)phl, nullptr, nullptr, Nn, 2 * Hd, Hd);

    // ---- GNN layer 1 ----
    cudaMemsetAsync(pmsg, 0, sizeof(float) * (size_t)Nn * Hd);
    k_scatter<<<CDIV(nedges * 128, 256), 256>>>(ei, nedges, (const float*)phl, (float*)pmsg);
    k_mma<2, false, false, false, true, 1, false, false>
        <<<dim3(Hd / 128, MT), 256>>>(
        (const float*)phl, (const float*)pmsg, nullptr,
        Wself + (size_t)Hd * Hd, Wnbr + (size_t)Hd * Hd,
        nullptr, out, nullptr, nullptr, Nn, 2 * Hd, Hd);
}

// round 7
// speedup vs baseline: 2.1080x; 1.1895x over previous
#include <cuda_runtime.h>
#include <cuda_bf16.h>
#include <cstdint>

#define CDIV(a,b) (((a)+(b)-1)/(b))

constexpr int Nn  = 50000;
constexpr int Ed  = 256;
constexpr int Hd  = 512;
constexpr int NEx = 5;
constexpr int GHd = 128;

// ---------------- scratch (static device globals; no allocation) -------------
__device__ float g_ghid[(size_t)Nn * GHd];
__device__ int   g_lists[NEx * Nn];
__device__ float g_gatew[NEx * Nn];
__device__ int   g_counts[NEx];
__device__ float g_h1[(size_t)NEx * Nn * Hd];
__device__ float g_nf[(size_t)Nn * Hd];
__device__ float g_msg[(size_t)Nn * Hd];
__device__ float g_hl[(size_t)Nn * Hd];

// pre-split weights, [n][k] layout, bf16 hi/lo planes
constexpr size_t OFF_G   = 0;                       // 128 x 768
constexpr size_t OFF_E1  = 98304;                   // 5 x 512 x 256
constexpr size_t OFF_E2  = 753664;                  // 5 x 512 x 512
constexpr size_t OFF_GNN = 2064384;                 // 2 x 512 x 1024
constexpr size_t WTOT    = 3112960;
__device__ __nv_bfloat16 g_wbh[WTOT];
__device__ __nv_bfloat16 g_wbl[WTOT];

// ---------------- helpers ----------------------------------------------------
__device__ __forceinline__ float gelu_f(float x) {
    float t = tanhf(0.7978845608028654f * (x + 0.044715f * x * x * x));
    return 0.5f * x * (1.0f + t);
}

__device__ __forceinline__ uint32_t packbf(float lo, float hi) {
    __nv_bfloat162 h = __floats2bfloat162_rn(lo, hi);
    return *reinterpret_cast<uint32_t*>(&h);
}

__device__ __forceinline__ uint32_t smem_u32(const void* p) {
    uint32_t a;
    asm("{ .reg .u64 t; cvta.to.shared.u64 t, %1; cvt.u32.u64 %0, t; }"
        : "=r"(a) : "l"(p));
    return a;
}

__device__ __forceinline__ void mma16816(
    float (&c)[4], const uint32_t (&a)[4], const uint32_t (&b)[2])
{
    asm volatile(
        "mma.sync.aligned.m16n8k16.row.col.f32.bf16.bf16.f32 "
        "{%0,%1,%2,%3}, {%4,%5,%6,%7}, {%8,%9}, {%0,%1,%2,%3};"
        : "+f"(c[0]), "+f"(c[1]), "+f"(c[2]), "+f"(c[3])
        : "r"(a[0]), "r"(a[1]), "r"(a[2]), "r"(a[3]), "r"(b[0]), "r"(b[1]));
}

__device__ __forceinline__ void ldm_x4(uint32_t (&r)[4], uint32_t addr) {
    asm volatile("ldmatrix.sync.aligned.m8n8.x4.shared.b16 {%0,%1,%2,%3}, [%4];"
                 : "=r"(r[0]), "=r"(r[1]), "=r"(r[2]), "=r"(r[3]) : "r"(addr));
}

__device__ __forceinline__ void red2(float* p, float x, float y) {
    asm volatile("red.global.add.v2.f32 [%0], {%1,%2};"
                 :: "l"(p), "f"(x), "f"(y) : "memory");
}

// ---------------- weight prep: transpose + bf16 hi/lo split ------------------
// W: [Kw][N] fp32 (batched, stride Kw*N); out: [N][ldk] bf16 (batch stride N*ldk)
__global__ void k_wprep(const float* __restrict__ W,
                        __nv_bfloat16* __restrict__ oh,
                        __nv_bfloat16* __restrict__ ol,
                        int Kw, int N, int ldk)
{
    int b = blockIdx.y;
    const float* Wp = W + (size_t)b * Kw * N;
    __nv_bfloat16* ohp = oh + (size_t)b * N * ldk;
    __nv_bfloat16* olp = ol + (size_t)b * N * ldk;
    int idx = blockIdx.x * blockDim.x + threadIdx.x;
    if (idx >= Kw * N) return;
    int k = idx / N, n = idx - k * N;
    float x = Wp[idx];
    __nv_bfloat16 h = __float2bfloat16(x);
    ohp[(size_t)n * ldk + k] = h;
    olp[(size_t)n * ldk + k] = __float2bfloat16(x - __bfloat162float(h));
}

// ---------------- bf16x3 tensor-core GEMM (128x128 tile, BK=32) --------------
// 256 thr = 8 warps (2x4), warp tile 64x32, ldmatrix fragments,
// double-buffered smem, pre-split B, 3-pass hi/lo accumulation.
constexpr int PB    = 128 * 40 * 2;        // bytes per plane (10240)
constexpr int DSMEM = 8 * PB;              // 2 buffers x 4 planes = 81920

template<int NSRC, bool ESEL, bool AEXP, bool GATHER, int ACT, bool SCATTER, bool EXPERT>
__global__ void __launch_bounds__(256) k_mma(
    const float* __restrict__ A0, const float* __restrict__ A1,
    const float* __restrict__ A2,
    const __nv_bfloat16* __restrict__ Bh, const __nv_bfloat16* __restrict__ Bl,
    const float* __restrict__ bias, float* __restrict__ C,
    const int* __restrict__ rowlist, const float* __restrict__ gatew,
    int Mfixed, int K, int NC)
{
    int M;
    const __nv_bfloat16* Bhp = Bh;
    const __nv_bfloat16* Blp = Bl;
    const float* biasp = bias;
    float*       Cp    = C;
    const int*   rl    = rowlist;
    const float* gwp   = gatew;
    const float* Asel  = A0;
    if (EXPERT) {
        int e = blockIdx.z;
        M = g_counts[e]; if (M > Nn) M = Nn;
        Bhp = Bh + (size_t)e * (size_t)NC * K;
        Blp = Bl + (size_t)e * (size_t)NC * K;
        if (bias) biasp = bias + (size_t)e * NC;
        if (ESEL) {
            const int map[NEx] = { 1, 2, 0, 0, 2 };  // tab, str, text, text, str
            int s = map[e];
            Asel = (s == 0) ? A0 : ((s == 1) ? A1 : A2);
        }
        if (AEXP) Asel = A0 + (size_t)e * (size_t)Nn * K;
        rl  = rowlist + e * Nn;
        gwp = gatew   + e * Nn;
        if (!SCATTER) Cp = C + (size_t)e * (size_t)Nn * NC;
    } else {
        M = Mfixed;
    }
    if ((int)(blockIdx.y * 128) >= M) return;

    extern __shared__ __nv_bfloat16 sm[];
    const uint32_t smb = smem_u32(sm);

    const int tid  = threadIdx.x;
    const int warp = tid >> 5, lane = tid & 31;
    const int wm = warp >> 2, wn = warp & 3;      // warp tile: 64 x 32
    const int gid = lane >> 2, tig = lane & 3;
    const int row0 = blockIdx.y * 128;
    const int col0 = blockIdx.x * 128;

    // ---- A loader: row am, 16 k-values at ak ----
    const int am = tid >> 1;
    const int ak = (tid & 1) << 4;
    const bool avalid = (row0 + am) < M;
    int arow = row0 + am;
    if (GATHER) {
        arow = avalid ? rl[arow] : 0;
        if ((unsigned)arow >= (unsigned)Nn) arow = 0;
    } else if (!avalid) arow = 0;

    auto aload = [&](int k0, float4 (&d)[4]) {
        if (!avalid) {
            d[0] = d[1] = d[2] = d[3] = make_float4(0.f, 0.f, 0.f, 0.f);
            return;
        }
        int kg = k0 + ak;
        const float* p;
        if (NSRC == 3) {
            const float* s = (kg < 256) ? A0 : ((kg < 512) ? A1 : A2);
            p = s + (size_t)arow * 256 + (kg & 255);
        } else if (NSRC == 2) {
            const float* s = (kg < 512) ? A0 : A1;
            p = s + (size_t)arow * 512 + (kg & 511);
        } else {
            p = Asel + (size_t)arow * (size_t)K + kg;
        }
        #pragma unroll
        for (int q = 0; q < 4; q++) d[q] = *(const float4*)(p + q * 4);
    };

    // ---- B loader: pre-split bf16, [n][k], fully coalesced ----
    const int bn = tid >> 1;
    const int bk = (tid & 1) << 4;
    const __nv_bfloat16* bhrow = Bhp + (size_t)(col0 + bn) * K + bk;
    const __nv_bfloat16* blrow = Blp + (size_t)(col0 + bn) * K + bk;
    auto bload = [&](int k0, uint4 (&dh)[2], uint4 (&dl)[2]) {
        const uint4* ph = (const uint4*)(bhrow + k0);
        const uint4* pl = (const uint4*)(blrow + k0);
        dh[0] = ph[0]; dh[1] = ph[1];
        dl[0] = pl[0]; dl[1] = pl[1];
    };

    // ---- stage regs -> smem (split A into hi/lo, copy B) ----
    auto store = [&](int b, const float4 (&av)[4], const uint4 (&bvh)[2],
                     const uint4 (&bvl)[2]) {
        __nv_bfloat16* base = sm + (size_t)b * (4 * PB / 2);
        uint32_t* ah = (uint32_t*)(base + am * 40 + ak);
        uint32_t* al = (uint32_t*)(base + (PB / 2) + am * 40 + ak);
        #pragma unroll
        for (int q = 0; q < 4; q++) {
            float4 v = av[q];
            uint32_t hp0 = packbf(v.x, v.y);
            uint32_t hp1 = packbf(v.z, v.w);
            __nv_bfloat162 h0 = *reinterpret_cast<__nv_bfloat162*>(&hp0);
            __nv_bfloat162 h1 = *reinterpret_cast<__nv_bfloat162*>(&hp1);
            ah[q * 2]     = hp0;
            ah[q * 2 + 1] = hp1;
            al[q * 2]     = packbf(v.x - __low2float(h0), v.y - __high2float(h0));
            al[q * 2 + 1] = packbf(v.z - __low2float(h1), v.w - __high2float(h1));
        }
        *(uint4*)(base + PB + bn * 40 + bk)            = bvh[0];
        *(uint4*)(base + PB + bn * 40 + bk + 8)        = bvh[1];
        *(uint4*)(base + PB + (PB / 2) + bn * 40 + bk)     = bvl[0];
        *(uint4*)(base + PB + (PB / 2) + bn * 40 + bk + 8) = bvl[1];
    };

    float c[4][4][4];
    #pragma unroll
    for (int i = 0; i < 4; i++)
        #pragma unroll
        for (int j = 0; j < 4; j++)
            #pragma unroll
            for (int q = 0; q < 4; q++) c[i][j][q] = 0.f;

    // ldmatrix lane geometry (same formula for A and B tiles)
    const int ltr = lane & 7;                 // row within 8x8 tile
    const int lt8 = ((lane >> 3) & 1) * 8;    // +8 rows for second tile
    const int lk8 = (lane >> 4) * 8;          // +8 k for upper tiles

    auto compute = [&](int b) {
        const uint32_t sbase = smb + (uint32_t)b * 4 * PB;
        #pragma unroll
        for (int ks = 0; ks < 32; ks += 16) {
            uint32_t bfh[4][2], bfl[4][2];
            #pragma unroll
            for (int jp = 0; jp < 2; jp++) {
                // lanes 0-7:(nj0,k0) 8-15:(nj0,k8) 16-23:(nj1,k0) 24-31:(nj1,k8)
                int nrow = wn * 32 + (jp * 2 + (lane >> 4)) * 8 + ltr;
                int koff = ks + ((lane >> 3) & 1) * 8;
                uint32_t addr = sbase + 2 * PB + (uint32_t)(nrow * 40 + koff) * 2;
                uint32_t r[4];
                ldm_x4(r, addr);
                bfh[jp*2][0] = r[0]; bfh[jp*2][1] = r[1];
                bfh[jp*2+1][0] = r[2]; bfh[jp*2+1][1] = r[3];
                ldm_x4(r, addr + PB);
                bfl[jp*2][0] = r[0]; bfl[jp*2][1] = r[1];
                bfl[jp*2+1][0] = r[2]; bfl[jp*2+1][1] = r[3];
            }
            #pragma unroll
            for (int mi = 0; mi < 4; mi++) {
                int mrow = wm * 64 + mi * 16 + lt8 + ltr;
                int koff = ks + lk8;
                uint32_t addr = sbase + (uint32_t)(mrow * 40 + koff) * 2;
                uint32_t ah[4], al[4];
                ldm_x4(ah, addr);
                ldm_x4(al, addr + PB);
                #pragma unroll
                for (int nj = 0; nj < 4; nj++) {
                    mma16816(c[mi][nj], ah, bfh[nj]);   // Ah*Bh
                    mma16816(c[mi][nj], ah, bfl[nj]);   // Ah*Bl
                    mma16816(c[mi][nj], al, bfh[nj]);   // Al*Bh
                }
            }
        }
    };

    const int nch = K >> 5;
    float4 apre[4]; uint4 bph[2], bpl[2];
    aload(0, apre); bload(0, bph, bpl);
    store(0, apre, bph, bpl);
    __syncthreads();

    for (int ch = 0; ch < nch; ch++) {
        if (ch + 1 < nch) { aload((ch + 1) << 5, apre); bload((ch + 1) << 5, bph, bpl); }
        compute(ch & 1);
        if (ch + 1 < nch) {
            store((ch + 1) & 1, apre, bph, bpl);
            __syncthreads();
        }
    }

    // ---- epilogue ----
    #pragma unroll
    for (int mi = 0; mi < 4; mi++) {
        #pragma unroll
        for (int h = 0; h < 2; h++) {
            int rg = row0 + wm * 64 + mi * 16 + gid + h * 8;
            if (rg >= M) continue;
            float gw = 0.f;
            float* dst = nullptr;
            if (SCATTER) {
                int node = rl[rg];
                gw = gwp[rg];
                if ((unsigned)node < (unsigned)Nn) dst = Cp + (size_t)node * NC;
            }
            #pragma unroll
            for (int nj = 0; nj < 4; nj++) {
                int col = col0 + wn * 32 + nj * 8 + tig * 2;
                float vx = c[mi][nj][h * 2 + 0];
                float vy = c[mi][nj][h * 2 + 1];
                if (biasp) { vx += biasp[col]; vy += biasp[col + 1]; }
                if (ACT == 1) { vx = fmaxf(vx, 0.f); vy = fmaxf(vy, 0.f); }
                else if (ACT == 2) { vx = gelu_f(vx); vy = gelu_f(vy); }
                if (SCATTER) {
                    if (dst) red2(dst + col, gw * vx, gw * vy);
                } else {
                    *(float2*)(Cp + (size_t)rg * NC + col) = make_float2(vx, vy);
                }
            }
        }
    }
}

// ---------------- gating head: logits -> softmax -> top2 -> routing lists ----
__global__ void k_gate(const float* __restrict__ Wg2, const float* __restrict__ bg2) {
    __shared__ int   scnt[NEx], sbase[NEx];
    __shared__ int   se[64];
    __shared__ int   snode[64];
    __shared__ int   spos[64];
    __shared__ float sg[64];

    const int tid = threadIdx.x;
    if (tid < NEx) scnt[tid] = 0;
    __syncthreads();

    const int warp = tid >> 5, lane = tid & 31;
    const int node = blockIdx.x * 32 + warp;

    if (node < Nn) {
        const float* gr = g_ghid + (size_t)node * GHd;
        float v0 = gr[lane], v1 = gr[lane + 32], v2 = gr[lane + 64], v3 = gr[lane + 96];
        float l[NEx];
        #pragma unroll
        for (int e = 0; e < NEx; e++) {
            float p = v0 * Wg2[lane * NEx + e]
                    + v1 * Wg2[(lane + 32) * NEx + e]
                    + v2 * Wg2[(lane + 64) * NEx + e]
                    + v3 * Wg2[(lane + 96) * NEx + e];
            #pragma unroll
            for (int off = 16; off > 0; off >>= 1)
                p += __shfl_xor_sync(0xffffffffu, p, off);
            l[e] = p;
        }
        if (lane == 0) {
            #pragma unroll
            for (int e = 0; e < NEx; e++) l[e] += bg2[e];
            int e0 = 0;
            #pragma unroll
            for (int e = 1; e < NEx; e++) if (l[e] > l[e0]) e0 = e;
            int e1 = -1;
            #pragma unroll
            for (int e = 0; e < NEx; e++)
                if (e != e0 && (e1 < 0 || l[e] > l[e1])) e1 = e;
            float gate0 = 1.f / (1.f + expf(l[e1] - l[e0]));
            float gate1 = 1.f - gate0;
            int s0 = warp * 2, s1 = warp * 2 + 1;
            se[s0] = e0; snode[s0] = node; sg[s0] = gate0;
            spos[s0] = atomicAdd(&scnt[e0], 1);
            se[s1] = e1; snode[s1] = node; sg[s1] = gate1;
            spos[s1] = atomicAdd(&scnt[e1], 1);
        }
    } else if (lane == 0) {
        se[warp * 2] = -1; se[warp * 2 + 1] = -1;
    }
    __syncthreads();
    if (tid < NEx) sbase[tid] = atomicAdd(&g_counts[tid], scnt[tid]);
    __syncthreads();
    if (tid < 64 && se[tid] >= 0) {
        int e = se[tid];
        int p = sbase[e] + spos[tid];
        if (p >= 0 && p < Nn) {
            g_lists[e * Nn + p] = snode[tid];
            g_gatew[e * Nn + p] = sg[tid];
        }
    }
}

// ---------------- edge segment-sum: agg[dst] += h[src] -----------------------
__global__ void k_scatter(const int* __restrict__ ei, int nedges,
                          const float* __restrict__ h, float* __restrict__ agg)
{
    int idx = blockIdx.x * blockDim.x + threadIdx.x;
    int eidx = idx >> 7;
    int t = idx & 127;
    if (eidx >= nedges) return;
    int s = ei[eidx];
    int d = ei[nedges + eidx];
    if ((unsigned)s >= (unsigned)Nn || (unsigned)d >= (unsigned)Nn) return;
    float4 v = ((const float4*)(h + (size_t)s * Hd))[t];
    atomicAdd((float4*)(agg + (size_t)d * Hd + (size_t)t * 4), v);
}

// ---------------- launch -----------------------------------------------------
extern "C" void kernel_launch(void* const* d_in, const int* in_sizes, int n_in,
                              void* d_out, int out_size)
{
    const float* text = (const float*)d_in[0];
    const float* tab  = (const float*)d_in[1];
    const float* str  = (const float*)d_in[2];
    const int*   ei   = (const int*)d_in[3];
    const float* Wg1  = (const float*)d_in[4];
    const float* bg1  = (const float*)d_in[5];
    const float* Wg2  = (const float*)d_in[6];
    const float* bg2  = (const float*)d_in[7];
    const float* We1  = (const float*)d_in[8];
    const float* be1  = (const float*)d_in[9];
    const float* We2  = (const float*)d_in[10];
    const float* be2  = (const float*)d_in[11];
    const float* Wself = (const float*)d_in[12];
    const float* Wnbr  = (const float*)d_in[13];
    float* out = (float*)d_out;
    const int nedges = in_sizes[3] / 2;

    void *pcnt, *pghid, *pnf, *pmsg, *phl, *ph1, *plists, *pgatew, *pwh, *pwl;
    cudaGetSymbolAddress(&pcnt,   g_counts);
    cudaGetSymbolAddress(&pghid,  g_ghid);
    cudaGetSymbolAddress(&pnf,    g_nf);
    cudaGetSymbolAddress(&pmsg,   g_msg);
    cudaGetSymbolAddress(&phl,    g_hl);
    cudaGetSymbolAddress(&ph1,    g_h1);
    cudaGetSymbolAddress(&plists, g_lists);
    cudaGetSymbolAddress(&pgatew, g_gatew);
    cudaGetSymbolAddress(&pwh,    g_wbh);
    cudaGetSymbolAddress(&pwl,    g_wbl);
    __nv_bfloat16* wbh = (__nv_bfloat16*)pwh;
    __nv_bfloat16* wbl = (__nv_bfloat16*)pwl;

    auto kG   = k_mma<3, false, false, false, 1, false, false>;
    auto kE1  = k_mma<1, true,  false, true,  2, false, true>;
    auto kE2  = k_mma<1, false, true,  false, 0, true,  true>;
    auto kGNN = k_mma<2, false, false, false, 1, false, false>;
    cudaFuncSetAttribute(kG,   cudaFuncAttributeMaxDynamicSharedMemorySize, DSMEM);
    cudaFuncSetAttribute(kE1,  cudaFuncAttributeMaxDynamicSharedMemorySize, DSMEM);
    cudaFuncSetAttribute(kE2,  cudaFuncAttributeMaxDynamicSharedMemorySize, DSMEM);
    cudaFuncSetAttribute(kGNN, cudaFuncAttributeMaxDynamicSharedMemorySize, DSMEM);

    cudaMemsetAsync(pcnt, 0, sizeof(int) * NEx);
    cudaMemsetAsync(pnf,  0, sizeof(float) * (size_t)Nn * Hd);

    // 0) pre-split all weights into [n][k] bf16 hi/lo planes
    k_wprep<<<dim3(CDIV(768 * 128, 256), 1), 256>>>(Wg1,  wbh + OFF_G,  wbl + OFF_G,  768, 128, 768);
    k_wprep<<<dim3(CDIV(256 * 512, 256), NEx), 256>>>(We1, wbh + OFF_E1, wbl + OFF_E1, 256, 512, 256);
    k_wprep<<<dim3(CDIV(512 * 512, 256), NEx), 256>>>(We2, wbh + OFF_E2, wbl + OFF_E2, 512, 512, 512);
    k_wprep<<<dim3(CDIV(512 * 512, 256), 2), 256>>>(Wself, wbh + OFF_GNN,       wbl + OFF_GNN,       512, 512, 1024);
    k_wprep<<<dim3(CDIV(512 * 512, 256), 2), 256>>>(Wnbr,  wbh + OFF_GNN + 512, wbl + OFF_GNN + 512, 512, 512, 1024);

    const int MT = CDIV(Nn, 128);

    // 1) gating hidden: relu([text|tab|str] @ Wg1 + bg1)
    kG<<<dim3(1, MT), 256, DSMEM>>>(
        text, tab, str, wbh + OFF_G, wbl + OFF_G, bg1, (float*)pghid,
        nullptr, nullptr, Nn, 3 * Ed, GHd);

    // 2) gating head: softmax top-2, build routing lists
    k_gate<<<CDIV(Nn, 32), 1024>>>(Wg2, bg2);

    // 3) expert MLP layer 1 (gathered rows, gelu), all 5 experts
    kE1<<<dim3(Hd / 128, MT, NEx), 256, DSMEM>>>(
        text, tab, str, wbh + OFF_E1, wbl + OFF_E1, be1, (float*)ph1,
        (const int*)plists, (const float*)pgatew, 0, Ed, Hd);

    // 4) expert MLP layer 2, scatter gate*out into node_feats
    kE2<<<dim3(Hd / 128, MT, NEx), 256, DSMEM>>>(
        (const float*)ph1, nullptr, nullptr, wbh + OFF_E2, wbl + OFF_E2, be2, (float*)pnf,
        (const int*)plists, (const float*)pgatew, 0, Hd, Hd);

    // ---- GNN layer 0: h1 = relu([h | segsum(h)] @ [[Wself0],[Wnbr0]]) ----
    cudaMemsetAsync(pmsg, 0, sizeof(float) * (size_t)Nn * Hd);
    k_scatter<<<CDIV(nedges * 128, 256), 256>>>(ei, nedges, (const float*)pnf, (float*)pmsg);
    kGNN<<<dim3(Hd / 128, MT), 256, DSMEM>>>(
        (const float*)pnf, (const float*)pmsg, nullptr,
        wbh + OFF_GNN, wbl + OFF_GNN, nullptr, (float*)phl,
        nullptr, nullptr, Nn, 2 * Hd, Hd);

    // ---- GNN layer 1 ----
    cudaMemsetAsync(pmsg, 0, sizeof(float) * (size_t)Nn * Hd);
    k_scatter<<<CDIV(nedges * 128, 256), 256>>>(ei, nedges, (const float*)phl, (float*)pmsg);
    kGNN<<<dim3(Hd / 128, MT), 256, DSMEM>>>(
        (const float*)phl, (const float*)pmsg, nullptr,
        wbh + OFF_GNN + (size_t)512 * 1024, wbl + OFF_GNN + (size_t)512 * 1024,
        nullptr, out, nullptr, nullptr, Nn, 2 * Hd, Hd);
}